// round 3
// baseline (speedup 1.0000x reference)
#include <cuda_runtime.h>
#include <cstdint>

typedef unsigned long long u64;

// ---------- device scratch ----------
__device__ float g_feat[4 * 64 * 64 * 64];      // NHWC feat[pix][64]
__device__ float g_wk[4 * 64 * 64 * 100];       // softmaxed kernels
__device__ u64   g_wc2[4 * 256 * 8];            // k1 weights: [quarter][c][8] pairs (m,m+1)
__device__ u64   g_wp2[64 * 9 * 4 * 14];        // k2 weights: [i][t][p][14] pairs (k,k+1), padded

// ---------- f32x2 helpers ----------
__device__ __forceinline__ u64 pack2(float lo, float hi) {
    u64 r; asm("mov.b64 %0, {%1, %2};" : "=l"(r) : "f"(lo), "f"(hi)); return r;
}
__device__ __forceinline__ void unpack2(u64 v, float& lo, float& hi) {
    asm("mov.b64 {%0, %1}, %2;" : "=f"(lo), "=f"(hi) : "l"(v));
}
__device__ __forceinline__ u64 fma2(u64 a, u64 b, u64 c) {
    u64 d; asm("fma.rn.f32x2 %0, %1, %2, %3;" : "=l"(d) : "l"(a), "l"(b), "l"(c)); return d;
}

// ============================================================
// K0: pack weights
//   g_wc2[qr][c][j] = (Wc[qr*16+2j, c], Wc[qr*16+2j+1, c])          (8192)
//   g_wp2[i][t][p][kp] = (We[p*25+2kp, i, t], We[p*25+2kp+1, i, t]) (32256, zero-padded)
// ============================================================
__global__ void k0_pack(const float* __restrict__ Wc, const float* __restrict__ We) {
    int e = blockIdx.x * 256 + threadIdx.x;
    if (e < 8192) {
        int j = e & 7, c = (e >> 3) & 255, qr = e >> 11;
        int m0 = qr * 16 + 2 * j;
        g_wc2[e] = pack2(Wc[(size_t)m0 * 256 + c], Wc[(size_t)(m0 + 1) * 256 + c]);
    } else if (e < 8192 + 32256) {
        int e2 = e - 8192;
        int kp = e2 % 14;
        int p  = (e2 / 14) & 3;
        int t  = (e2 / 56) % 9;
        int i  = e2 / 504;
        int o0 = p * 25 + 2 * kp;
        float lo = (2 * kp < 25)     ? We[(size_t)o0 * 576 + i * 9 + t] : 0.f;
        float hi = (2 * kp + 1 < 25) ? We[(size_t)(o0 + 1) * 576 + i * 9 + t] : 0.f;
        g_wp2[e2] = pack2(lo, hi);
    }
}

// ============================================================
// K1: feat = relu(Wc @ x + bc), NHWC output, f32x2
//   grid 512 (128 px-groups x 4 m-quarters) x 128 threads
//   1 px/thread, 16 outputs (8 u64 acc), 16KB smem weights
// ============================================================
#define K1_SMEM (2048 * 8)

__global__ __launch_bounds__(128) void k1_compress(const float* __restrict__ x,
                                                   const float* __restrict__ bc) {
    extern __shared__ u64 ws[];      // [256][8] packed pairs for this quarter
    int tid = threadIdx.x;
    int qr  = blockIdx.x & 3;
    int pix = (blockIdx.x >> 2) * 128 + tid;

    const u64* src = g_wc2 + qr * 2048;
    for (int e = tid; e < 2048; e += 128) ws[e] = src[e];
    __syncthreads();

    int bb = pix >> 12, hw = pix & 4095;
    const float* xp = x + ((size_t)bb << 20) + hw;

    u64 acc[8];
#pragma unroll
    for (int j = 0; j < 8; j++) acc[j] = 0ull;

    for (int c = 0; c < 256; c += 4) {
        float xv[4];
#pragma unroll
        for (int u = 0; u < 4; u++) xv[u] = __ldg(xp + (size_t)(c + u) * 4096);
#pragma unroll
        for (int u = 0; u < 4; u++) {
            u64 v2 = pack2(xv[u], xv[u]);
            const ulonglong2* wr = (const ulonglong2*)(ws + (size_t)(c + u) * 8);
#pragma unroll
            for (int q = 0; q < 4; q++) {
                ulonglong2 ww = wr[q];
                acc[2 * q + 0] = fma2(v2, ww.x, acc[2 * q + 0]);
                acc[2 * q + 1] = fma2(v2, ww.y, acc[2 * q + 1]);
            }
        }
    }

    float* dst = g_feat + (size_t)pix * 64 + qr * 16;
#pragma unroll
    for (int q = 0; q < 4; q++) {
        float f0, f1, f2, f3;
        unpack2(acc[2 * q + 0], f0, f1);
        unpack2(acc[2 * q + 1], f2, f3);
        int m0 = qr * 16 + 4 * q;
        float4 v;
        v.x = fmaxf(f0 + __ldg(bc + m0 + 0), 0.f);
        v.y = fmaxf(f1 + __ldg(bc + m0 + 1), 0.f);
        v.z = fmaxf(f2 + __ldg(bc + m0 + 2), 0.f);
        v.w = fmaxf(f3 + __ldg(bc + m0 + 3), 0.f);
        ((float4*)dst)[q] = v;
    }
}

// ============================================================
// K2: 3x3 conv (64 -> 100) + bias + softmax over 25 taps
//   grid 256 (b, row) x 256 threads; thread = (x, p); 1 px, 25 outputs (13 u64)
//   warp = same p, contiguous x -> weight LDS broadcast, feat LDS stride-1
// ============================================================
#define K2_FS_BYTES (64 * 200 * 4)               // 51200
#define K2_WQ_BYTES (4032 * 8)                   // 32256 (one 8-i chunk)
#define K2_SMEM (K2_FS_BYTES + K2_WQ_BYTES)

__global__ __launch_bounds__(256) void k2_conv_softmax(const float* __restrict__ benc) {
    extern __shared__ char sm2[];
    float* fs = (float*)sm2;                     // [64 i][200] (3 rows x 66 cols)
    u64* wq = (u64*)(sm2 + K2_FS_BYTES);         // [8 ii][9 t][4 p][14]

    int tid = threadIdx.x;
    int bb = blockIdx.x >> 6;
    int y  = blockIdx.x & 63;
    int x  = tid & 63;
    int p  = tid >> 6;        // 0..3, constant per 2 warps

    // stage feat rows y-1..y+1, cols -1..64 (198 positions)
    for (int pos = tid; pos < 198; pos += 256) {
        int r = pos / 66, cc = pos % 66;
        int iy = y + r - 1, ix = cc - 1;
        if (((unsigned)iy < 64u) && ((unsigned)ix < 64u)) {
            const float4* s4 = (const float4*)(g_feat + ((size_t)((bb * 64 + iy) * 64 + ix) << 6));
#pragma unroll
            for (int i0 = 0; i0 < 64; i0 += 4) {
                float4 v = s4[i0 >> 2];
                fs[(i0 + 0) * 200 + pos] = v.x;
                fs[(i0 + 1) * 200 + pos] = v.y;
                fs[(i0 + 2) * 200 + pos] = v.z;
                fs[(i0 + 3) * 200 + pos] = v.w;
            }
        } else {
#pragma unroll
            for (int i0 = 0; i0 < 64; i0++) fs[i0 * 200 + pos] = 0.f;
        }
    }

    u64 acc[13];
#pragma unroll
    for (int j = 0; j < 13; j++) acc[j] = 0ull;

    for (int chunk = 0; chunk < 8; chunk++) {
        __syncthreads();
        for (int e = tid; e < 4032; e += 256) wq[e] = g_wp2[chunk * 4032 + e];
        __syncthreads();

#pragma unroll 1
        for (int ii = 0; ii < 8; ii++) {
            const float* fr = fs + (chunk * 8 + ii) * 200 + x;
            float vv[3][3];
#pragma unroll
            for (int dy = 0; dy < 3; dy++)
#pragma unroll
                for (int dx = 0; dx < 3; dx++) vv[dy][dx] = fr[dy * 66 + dx];
#pragma unroll
            for (int t = 0; t < 9; t++) {
                float v = vv[t / 3][t % 3];
                u64 v2 = pack2(v, v);
                const ulonglong2* wr = (const ulonglong2*)(wq + (size_t)((ii * 9 + t) * 4 + p) * 14);
#pragma unroll
                for (int q = 0; q < 6; q++) {
                    ulonglong2 ww = wr[q];
                    acc[2 * q + 0] = fma2(v2, ww.x, acc[2 * q + 0]);
                    acc[2 * q + 1] = fma2(v2, ww.y, acc[2 * q + 1]);
                }
                acc[12] = fma2(v2, wr[6].x, acc[12]);
            }
        }
    }

    // bias + softmax over the 25 taps + store
    float l[25];
#pragma unroll
    for (int kp = 0; kp < 13; kp++) {
        float lo, hi;
        unpack2(acc[kp], lo, hi);
        l[2 * kp] = lo;
        if (2 * kp + 1 < 25) l[2 * kp + 1] = hi;
    }
    float mx = -1e30f;
#pragma unroll
    for (int k = 0; k < 25; k++) {
        l[k] += __ldg(benc + p * 25 + k);
        mx = fmaxf(mx, l[k]);
    }
    float s = 0.f;
#pragma unroll
    for (int k = 0; k < 25; k++) {
        float e = __expf(l[k] - mx);
        l[k] = e;
        s += e;
    }
    float inv = 1.f / s;
    float* dst = g_wk + (size_t)((bb * 64 + y) * 64 + x) * 100 + p * 25;
#pragma unroll
    for (int k = 0; k < 25; k++) dst[k] = l[k] * inv;
}

// ============================================================
// K3: content-aware gather, channel-split x4 for occupancy
//   grid 1024 (b, h, cg) x 256 threads (w x p); 16 rounds of 4 channels
//   double-buffered smem, wk taps in registers
// ============================================================
__device__ __forceinline__ float4 fetch4(const float* __restrict__ x, int bb, int c, int h, int e) {
    int row = e / 68, col = e % 68;
    int iy = h + row - 2, ix = col - 2;
    float4 v = make_float4(0.f, 0.f, 0.f, 0.f);
    if ((unsigned)iy < 64u && (unsigned)ix < 64u) {
        const float* b = x + (((size_t)(bb * 256 + c)) << 12) + (iy << 6) + ix;
        v.x = __ldg(b);
        v.y = __ldg(b + 4096);
        v.z = __ldg(b + 8192);
        v.w = __ldg(b + 12288);
    }
    return v;
}

__global__ __launch_bounds__(256) void k3_gather(const float* __restrict__ x,
                                                 float* __restrict__ out) {
    __shared__ float wk_s[6400];          // 64 px x 100
    __shared__ float4 xs[2][340];         // 5 rows x 68 cols, 4 channels

    int tid = threadIdx.x;
    int cg = blockIdx.x & 3;              // channel group: 64 channels
    int h  = (blockIdx.x >> 2) & 63;
    int bb = blockIdx.x >> 8;
    int w = tid >> 2;
    int p = tid & 3;
    int cbase = cg * 64;

    // stage wk row
    {
        const float4* src = (const float4*)(g_wk + (size_t)(bb * 4096 + h * 64) * 100);
        float4* dst = (float4*)wk_s;
        for (int i = tid; i < 1600; i += 256) dst[i] = src[i];
    }

    int e1 = tid;
    int e2 = tid + 256;
    bool has2 = (e2 < 340);

    float4 pf1 = fetch4(x, bb, cbase, h, e1);
    float4 pf2 = has2 ? fetch4(x, bb, cbase, h, e2) : make_float4(0, 0, 0, 0);
    xs[0][e1] = pf1;
    if (has2) xs[0][e2] = pf2;
    __syncthreads();

    u64 wk2[25];
#pragma unroll
    for (int k = 0; k < 25; k++) {
        float v = wk_s[w * 100 + p * 25 + k];
        wk2[k] = pack2(v, v);
    }

    size_t obase = ((size_t)(bb * 256 + cbase) * 4096 + (h << 6) + w) * 4 + p;

    for (int it = 0; it < 16; it++) {
        int cur = it & 1;
        if (it < 15) {
            pf1 = fetch4(x, bb, cbase + (it + 1) * 4, h, e1);
            if (has2) pf2 = fetch4(x, bb, cbase + (it + 1) * 4, h, e2);
        }

        u64 a01 = 0ull, a23 = 0ull;
        const ulonglong2* q = (const ulonglong2*)xs[cur];
#pragma unroll
        for (int k = 0; k < 25; k++) {
            int off = (k / 5) * 68 + w + (k % 5);
            ulonglong2 v = q[off];
            a01 = fma2(v.x, wk2[k], a01);
            a23 = fma2(v.y, wk2[k], a23);
        }

        if (it < 15) {
            xs[cur ^ 1][e1] = pf1;
            if (has2) xs[cur ^ 1][e2] = pf2;
        }

        float o0, o1, o2, o3;
        unpack2(a01, o0, o1);
        unpack2(a23, o2, o3);
        size_t ob = obase + (size_t)it * 4 * 16384;
        out[ob + 0 * 16384] = o0;
        out[ob + 1 * 16384] = o1;
        out[ob + 2 * 16384] = o2;
        out[ob + 3 * 16384] = o3;

        __syncthreads();
    }
}

// ============================================================
// launch
// ============================================================
extern "C" void kernel_launch(void* const* d_in, const int* in_sizes, int n_in,
                              void* d_out, int out_size) {
    (void)in_sizes; (void)n_in; (void)out_size;
    const float* x     = (const float*)d_in[0];
    const float* Wcomp = (const float*)d_in[1];
    const float* bcomp = (const float*)d_in[2];
    const float* Wenc  = (const float*)d_in[3];
    const float* benc  = (const float*)d_in[4];
    float* out = (float*)d_out;

    cudaFuncSetAttribute(k1_compress, cudaFuncAttributeMaxDynamicSharedMemorySize, K1_SMEM);
    cudaFuncSetAttribute(k2_conv_softmax, cudaFuncAttributeMaxDynamicSharedMemorySize, K2_SMEM);

    k0_pack<<<(8192 + 32256 + 255) / 256, 256>>>(Wcomp, Wenc);
    k1_compress<<<512, 128, K1_SMEM>>>(x, bcomp);
    k2_conv_softmax<<<256, 256, K2_SMEM>>>(benc);
    k3_gather<<<1024, 256>>>(x, out);
}

// round 4
// speedup vs baseline: 1.0543x; 1.0543x over previous
#include <cuda_runtime.h>
#include <cstdint>

typedef unsigned long long u64;

// ---------- device scratch ----------
__device__ float g_feat2[64 * 4 * 64 * 64];     // NCHW feat2[((m*4+b)*64+y)*64+x]
__device__ float g_wk[4 * 64 * 64 * 100];       // softmaxed kernels
__device__ u64   g_wc2[4 * 256 * 8];            // k1 weights: [quarter][c][8] pairs (m,m+1)
__device__ u64   g_wp3[4 * 64 * 9 * 14];        // k2 weights: [p][i][t][14] pairs (k,k+1), padded

// ---------- f32x2 helpers ----------
__device__ __forceinline__ u64 pack2(float lo, float hi) {
    u64 r; asm("mov.b64 %0, {%1, %2};" : "=l"(r) : "f"(lo), "f"(hi)); return r;
}
__device__ __forceinline__ void unpack2(u64 v, float& lo, float& hi) {
    asm("mov.b64 {%0, %1}, %2;" : "=f"(lo), "=f"(hi) : "l"(v));
}
__device__ __forceinline__ u64 fma2(u64 a, u64 b, u64 c) {
    u64 d; asm("fma.rn.f32x2 %0, %1, %2, %3;" : "=l"(d) : "l"(a), "l"(b), "l"(c)); return d;
}

// ============================================================
// K0: pack weights
//   g_wc2[qr][c][j]     = (Wc[qr*16+2j, c], Wc[qr*16+2j+1, c])        (8192)
//   g_wp3[p][i][t][kp]  = (We[p*25+2kp, i, t], We[p*25+2kp+1, i, t])  (32256, padded)
// ============================================================
__global__ void k0_pack(const float* __restrict__ Wc, const float* __restrict__ We) {
    int e = blockIdx.x * 256 + threadIdx.x;
    if (e < 8192) {
        int j = e & 7, c = (e >> 3) & 255, qr = e >> 11;
        int m0 = qr * 16 + 2 * j;
        g_wc2[e] = pack2(Wc[(size_t)m0 * 256 + c], Wc[(size_t)(m0 + 1) * 256 + c]);
    } else if (e < 8192 + 32256) {
        int e2 = e - 8192;
        int kp = e2 % 14;
        int t  = (e2 / 14) % 9;
        int i  = (e2 / 126) % 64;
        int p  = e2 / 8064;
        int o0 = p * 25 + 2 * kp;
        float lo = (2 * kp < 25)     ? We[(size_t)o0 * 576 + i * 9 + t] : 0.f;
        float hi = (2 * kp + 1 < 25) ? We[(size_t)(o0 + 1) * 576 + i * 9 + t] : 0.f;
        g_wp3[e2] = pack2(lo, hi);
    }
}

// ============================================================
// K1: feat = relu(Wc @ x + bc), NCHW output
//   grid 512 (128 px-groups x 4 m-quarters) x 128 threads
//   1 px/thread, 16 outputs (8 u64 acc), 16KB smem weights
// ============================================================
#define K1_SMEM (2048 * 8)

__global__ __launch_bounds__(128) void k1_compress(const float* __restrict__ x,
                                                   const float* __restrict__ bc) {
    extern __shared__ u64 ws[];      // [256][8] packed pairs for this quarter
    int tid = threadIdx.x;
    int qr  = blockIdx.x & 3;
    int pix = (blockIdx.x >> 2) * 128 + tid;

    const u64* src = g_wc2 + qr * 2048;
    for (int e = tid; e < 2048; e += 128) ws[e] = src[e];
    __syncthreads();

    int bb = pix >> 12, hw = pix & 4095;
    const float* xp = x + ((size_t)bb << 20) + hw;

    u64 acc[8];
#pragma unroll
    for (int j = 0; j < 8; j++) acc[j] = 0ull;

    for (int c = 0; c < 256; c += 4) {
        float xv[4];
#pragma unroll
        for (int u = 0; u < 4; u++) xv[u] = __ldg(xp + (size_t)(c + u) * 4096);
#pragma unroll
        for (int u = 0; u < 4; u++) {
            u64 v2 = pack2(xv[u], xv[u]);
            const ulonglong2* wr = (const ulonglong2*)(ws + (size_t)(c + u) * 8);
#pragma unroll
            for (int q = 0; q < 4; q++) {
                ulonglong2 ww = wr[q];
                acc[2 * q + 0] = fma2(v2, ww.x, acc[2 * q + 0]);
                acc[2 * q + 1] = fma2(v2, ww.y, acc[2 * q + 1]);
            }
        }
    }

    // NCHW store: feat2[(m*4+bb)*4096 + hw], coalesced across warp
#pragma unroll
    for (int j = 0; j < 8; j++) {
        float f0, f1;
        unpack2(acc[j], f0, f1);
        int m0 = qr * 16 + 2 * j;
        f0 = fmaxf(f0 + __ldg(bc + m0 + 0), 0.f);
        f1 = fmaxf(f1 + __ldg(bc + m0 + 1), 0.f);
        g_feat2[(size_t)(m0 * 4 + bb) * 4096 + hw] = f0;
        g_feat2[(size_t)((m0 + 1) * 4 + bb) * 4096 + hw] = f1;
    }
}

// ============================================================
// K2: 3x3 conv (64 -> 100) + bias + softmax over 25 taps
//   grid 512 (b, row-pair, p) x 128 threads; thread = one pixel, 25 outputs
//   feat read directly from NCHW global (coalesced, L2-resident);
//   weights for this p chunked 32-i into 32.25KB smem (4 barriers total)
// ============================================================
#define K2_SMEM (4032 * 8)   // 32.25 KB

__global__ __launch_bounds__(128) void k2_conv_softmax(const float* __restrict__ benc) {
    extern __shared__ u64 wq[];        // [32 i][9 t][14 kp]
    int tid = threadIdx.x;
    int p  = blockIdx.x & 3;
    int yp = (blockIdx.x >> 2) & 31;
    int bb = blockIdx.x >> 7;
    int x  = tid & 63;
    int y  = yp * 2 + (tid >> 6);

    bool rowok0 = (y - 1) >= 0, rowok2 = (y + 1) < 64;
    bool colok0 = (x - 1) >= 0, colok2 = (x + 1) < 64;

    u64 acc[13];
#pragma unroll
    for (int j = 0; j < 13; j++) acc[j] = 0ull;

    const float* fbase = g_feat2 + ((size_t)bb << 12) + (y << 6) + x;

    for (int ci = 0; ci < 2; ci++) {
        __syncthreads();
        {
            const ulonglong2* src = (const ulonglong2*)(g_wp3 + (size_t)p * 8064 + ci * 4032);
            ulonglong2* dst = (ulonglong2*)wq;
            for (int e = tid; e < 2016; e += 128) dst[e] = src[e];
        }
        __syncthreads();

#pragma unroll 2
        for (int ii = 0; ii < 32; ii++) {
            int i = ci * 32 + ii;
            const float* fp = fbase + ((size_t)i << 14);   // i*4*4096
            float f[9];
#pragma unroll
            for (int t = 0; t < 9; t++) {
                int dy = t / 3 - 1, dx = t % 3 - 1;
                bool ok = (dy == 0 || (dy < 0 ? rowok0 : rowok2)) &&
                          (dx == 0 || (dx < 0 ? colok0 : colok2));
                f[t] = ok ? __ldg(fp + dy * 64 + dx) : 0.f;
            }
#pragma unroll
            for (int t = 0; t < 9; t++) {
                u64 v2 = pack2(f[t], f[t]);
                const ulonglong2* wr = (const ulonglong2*)(wq + (size_t)(ii * 9 + t) * 14);
#pragma unroll
                for (int q = 0; q < 6; q++) {
                    ulonglong2 ww = wr[q];
                    acc[2 * q + 0] = fma2(v2, ww.x, acc[2 * q + 0]);
                    acc[2 * q + 1] = fma2(v2, ww.y, acc[2 * q + 1]);
                }
                acc[12] = fma2(v2, wr[6].x, acc[12]);
            }
        }
    }

    // bias + softmax over 25 taps + store
    float l[25];
#pragma unroll
    for (int kp = 0; kp < 13; kp++) {
        float lo, hi;
        unpack2(acc[kp], lo, hi);
        l[2 * kp] = lo;
        if (2 * kp + 1 < 25) l[2 * kp + 1] = hi;
    }
    float mx = -1e30f;
#pragma unroll
    for (int k = 0; k < 25; k++) {
        l[k] += __ldg(benc + p * 25 + k);
        mx = fmaxf(mx, l[k]);
    }
    float s = 0.f;
#pragma unroll
    for (int k = 0; k < 25; k++) {
        float e = __expf(l[k] - mx);
        l[k] = e;
        s += e;
    }
    float inv = 1.f / s;
    float* dst = g_wk + (size_t)((bb * 64 + y) * 64 + x) * 100 + p * 25;
#pragma unroll
    for (int k = 0; k < 25; k++) dst[k] = l[k] * inv;
}

// ============================================================
// K3: content-aware gather, channel-split x4 (unchanged from R3: 41.2us known)
// ============================================================
__device__ __forceinline__ float4 fetch4(const float* __restrict__ x, int bb, int c, int h, int e) {
    int row = e / 68, col = e % 68;
    int iy = h + row - 2, ix = col - 2;
    float4 v = make_float4(0.f, 0.f, 0.f, 0.f);
    if ((unsigned)iy < 64u && (unsigned)ix < 64u) {
        const float* b = x + (((size_t)(bb * 256 + c)) << 12) + (iy << 6) + ix;
        v.x = __ldg(b);
        v.y = __ldg(b + 4096);
        v.z = __ldg(b + 8192);
        v.w = __ldg(b + 12288);
    }
    return v;
}

__global__ __launch_bounds__(256) void k3_gather(const float* __restrict__ x,
                                                 float* __restrict__ out) {
    __shared__ float wk_s[6400];          // 64 px x 100
    __shared__ float4 xs[2][340];         // 5 rows x 68 cols, 4 channels

    int tid = threadIdx.x;
    int cg = blockIdx.x & 3;              // channel group: 64 channels
    int h  = (blockIdx.x >> 2) & 63;
    int bb = blockIdx.x >> 8;
    int w = tid >> 2;
    int p = tid & 3;
    int cbase = cg * 64;

    {
        const float4* src = (const float4*)(g_wk + (size_t)(bb * 4096 + h * 64) * 100);
        float4* dst = (float4*)wk_s;
        for (int i = tid; i < 1600; i += 256) dst[i] = src[i];
    }

    int e1 = tid;
    int e2 = tid + 256;
    bool has2 = (e2 < 340);

    float4 pf1 = fetch4(x, bb, cbase, h, e1);
    float4 pf2 = has2 ? fetch4(x, bb, cbase, h, e2) : make_float4(0, 0, 0, 0);
    xs[0][e1] = pf1;
    if (has2) xs[0][e2] = pf2;
    __syncthreads();

    u64 wk2[25];
#pragma unroll
    for (int k = 0; k < 25; k++) {
        float v = wk_s[w * 100 + p * 25 + k];
        wk2[k] = pack2(v, v);
    }

    size_t obase = ((size_t)(bb * 256 + cbase) * 4096 + (h << 6) + w) * 4 + p;

    for (int it = 0; it < 16; it++) {
        int cur = it & 1;
        if (it < 15) {
            pf1 = fetch4(x, bb, cbase + (it + 1) * 4, h, e1);
            if (has2) pf2 = fetch4(x, bb, cbase + (it + 1) * 4, h, e2);
        }

        u64 a01 = 0ull, a23 = 0ull;
        const ulonglong2* q = (const ulonglong2*)xs[cur];
#pragma unroll
        for (int k = 0; k < 25; k++) {
            int off = (k / 5) * 68 + w + (k % 5);
            ulonglong2 v = q[off];
            a01 = fma2(v.x, wk2[k], a01);
            a23 = fma2(v.y, wk2[k], a23);
        }

        if (it < 15) {
            xs[cur ^ 1][e1] = pf1;
            if (has2) xs[cur ^ 1][e2] = pf2;
        }

        float o0, o1, o2, o3;
        unpack2(a01, o0, o1);
        unpack2(a23, o2, o3);
        size_t ob = obase + (size_t)it * 4 * 16384;
        out[ob + 0 * 16384] = o0;
        out[ob + 1 * 16384] = o1;
        out[ob + 2 * 16384] = o2;
        out[ob + 3 * 16384] = o3;

        __syncthreads();
    }
}

// ============================================================
// launch
// ============================================================
extern "C" void kernel_launch(void* const* d_in, const int* in_sizes, int n_in,
                              void* d_out, int out_size) {
    (void)in_sizes; (void)n_in; (void)out_size;
    const float* x     = (const float*)d_in[0];
    const float* Wcomp = (const float*)d_in[1];
    const float* bcomp = (const float*)d_in[2];
    const float* Wenc  = (const float*)d_in[3];
    const float* benc  = (const float*)d_in[4];
    float* out = (float*)d_out;

    cudaFuncSetAttribute(k1_compress, cudaFuncAttributeMaxDynamicSharedMemorySize, K1_SMEM);
    cudaFuncSetAttribute(k2_conv_softmax, cudaFuncAttributeMaxDynamicSharedMemorySize, K2_SMEM);

    k0_pack<<<(8192 + 32256 + 255) / 256, 256>>>(Wcomp, Wenc);
    k1_compress<<<512, 128, K1_SMEM>>>(x, bcomp);
    k2_conv_softmax<<<512, 128, K2_SMEM>>>(benc);
    k3_gather<<<1024, 256>>>(x, out);
}